// round 15
// baseline (speedup 1.0000x reference)
#include <cuda_runtime.h>
#include <cuda_fp16.h>
#include <cstdint>

// ---------------------------------------------------------------------------
// VectorQuantizer on GB300 (sm_103a, compute_103 PTX) — single-pass fp16 MMA.
// 3 CTAs/SM (occ 37.5%): 8 x 128-code chunks, acc=32 regs. Block-shared
// running max via return-value atomicMax. Certified appends ~5/row; exact
// fp32 rescoring + fused loss. R15: prep kernels merged, nop dropped —
// replay chain is 2 launches (prep, main) instead of 4.
// ---------------------------------------------------------------------------

#define NCTA 2048
#define APITCH 72      // halves per A row (144 B; conflict-free ldmatrix)
#define A32P 65        // floats per A32 row
#define CAP 20         // candidate list capacity per row
#define FNINF 0xFF800000u
#define KEYNINF 0x007FFFFFu   // fkey(-inf)

// dynamic smem layout (bytes)
#define OFF_A16   0            // 64 * 144          =  9216
#define OFF_A32   9216         // 64 * 65 * 4       = 16640
#define OFF_CAND  25856        // 64 * 20 * 8       = 10240
#define OFF_ESUM  36096        // 1024 * 4          =  4096
#define OFF_B     40192        // 2 * 16384         = 32768
#define DSMEM     72960

__device__ __align__(16) __half g_Bimg[65536];   // 256 tiles(n8 x k32) * 512 B
__device__ __align__(16) float  g_esum[1024];
__device__ float g_losspart[NCTA];
__device__ int   g_ctr = 0;

__device__ __forceinline__ uint32_t smem_u32(const void* p) {
    uint32_t a;
    asm("{ .reg .u64 t; cvta.to.shared.u64 t, %1; cvt.u32.u64 %0, t; }" : "=r"(a) : "l"(p));
    return a;
}
__device__ __forceinline__ uint32_t fkey(float f) {          // monotonic float->uint
    uint32_t u = __float_as_uint(f);
    return u ^ ((u >> 31) ? 0xFFFFFFFFu : 0x80000000u);
}
__device__ __forceinline__ float funkey(uint32_t k) {        // inverse
    uint32_t u = (k & 0x80000000u) ? (k ^ 0x80000000u) : ~k;
    return __uint_as_float(u);
}
__device__ __forceinline__ void ldsm4(uint32_t a[4], uint32_t addr) {
    asm volatile("ldmatrix.sync.aligned.m8n8.x4.shared.b16 {%0,%1,%2,%3}, [%4];"
        : "=r"(a[0]), "=r"(a[1]), "=r"(a[2]), "=r"(a[3]) : "r"(addr));
}
__device__ __forceinline__ void mma16816(float c[4], const uint32_t a[4],
                                         uint32_t b0, uint32_t b1) {
    asm volatile("mma.sync.aligned.m16n8k16.row.col.f32.f16.f16.f32 "
        "{%0,%1,%2,%3}, {%4,%5,%6,%7}, {%8,%9}, {%0,%1,%2,%3};"
        : "+f"(c[0]), "+f"(c[1]), "+f"(c[2]), "+f"(c[3])
        : "r"(a[0]), "r"(a[1]), "r"(a[2]), "r"(a[3]), "r"(b0), "r"(b1));
}
__device__ __forceinline__ void cpasync16(uint32_t sdst, const void* gsrc) {
    asm volatile("cp.async.cg.shared.global [%0], [%1], 16;" :: "r"(sdst), "l"(gsrc) : "memory");
}

// exact fp32 dot of a 64-elem row pair using float4 loads (L1-friendly)
__device__ __forceinline__ float dot64(const float* __restrict__ a,
                                       const float4* __restrict__ e4) {
    float dot = 0.f;
    #pragma unroll
    for (int i = 0; i < 16; i++) {
        float4 e = __ldg(e4 + i);
        dot = __fmaf_rn(a[i * 4 + 0], e.x, dot);
        dot = __fmaf_rn(a[i * 4 + 1], e.y, dot);
        dot = __fmaf_rn(a[i * 4 + 2], e.z, dot);
        dot = __fmaf_rn(a[i * 4 + 3], e.w, dot);
    }
    return dot;
}

// ---- merged prep: block 0 -> esum (exact R1 formula); blocks 1..128 -> B img
__global__ void vq_prep(const float* __restrict__ emb) {
    if (blockIdx.x == 0) {
        // esum for 1024 codes, 256 threads x 4 codes each
        #pragma unroll
        for (int r = 0; r < 4; r++) {
            int k = threadIdx.x + r * 256;
            float s = 0.f;
            #pragma unroll
            for (int d = 0; d < 64; d++) {
                float e = emb[k * 64 + d];
                s = __fadd_rn(s, __fmul_rn(e, e));
            }
            g_esum[k] = s;
        }
        return;
    }
    // B image (bhi only) in exact mma-fragment order
    int p = (blockIdx.x - 1) * 256 + threadIdx.x;   // 32768 u32 slots
    int tile = p >> 7, u = p & 127;
    int l = u >> 2, r = u & 3;
    int nt = tile >> 1, ks32 = tile & 1;
    int n = nt * 8 + (l >> 2);
    int q = l & 3;
    int kk = ks32 * 32 + ((r >> 1) << 4) + ((r & 1) << 3) + q * 2;
    __half2 out;
    #pragma unroll
    for (int j = 0; j < 2; j++) {
        int w = kk + j;
        float b = __fmul_rn(emb[n * 64 + w], 1024.0f);   // exact (2^10)
        if (j == 0) out.x = __float2half_rn(b); else out.y = __float2half_rn(b);
    }
    ((__half2*)g_Bimg)[p] = out;
}

// ---- main --------------------------------------------------------------------
__global__ void __launch_bounds__(256, 3)
vq_main(const float* __restrict__ z, const float* __restrict__ emb,
        float* __restrict__ zq_out, float* __restrict__ idx_out,
        float* __restrict__ loss_out, int do_zq, int do_idx, int do_loss) {
    extern __shared__ __align__(16) char dsm[];
    __half* A16 = (__half*)(dsm + OFF_A16);
    float*  A32 = (float*)(dsm + OFF_A32);
    unsigned long long* cand = (unsigned long long*)(dsm + OFF_CAND);
    float* esum_s = (float*)(dsm + OFF_ESUM);
    const uint32_t sB = smem_u32(dsm) + OFF_B;

    __shared__ float rowsum_s[64], rowthr_s[64];
    __shared__ uint32_t s_gkey[64];
    __shared__ int   cnt_s[64];
    __shared__ float s_bv[64];
    __shared__ int   s_last;

    const int tid = threadIdx.x, wid = tid >> 5, lane = tid & 31;
    const int mw = wid >> 2, nw = wid & 3;
    const int q = lane & 3;

    // ---- prefetch B chunk 0 FIRST so it overlaps the z prologue -------------
    {
        const char* src = (const char*)g_Bimg;
        #pragma unroll
        for (int i = 0; i < 4; i++)
            cpasync16(sB + tid * 16 + i * 4096, src + tid * 16 + i * 4096);
        asm volatile("cp.async.commit_group;" ::: "memory");
    }

    for (int i = tid; i < 1024; i += 256) esum_s[i] = g_esum[i];
    if (tid < 64) { cnt_s[tid] = 0; s_gkey[tid] = KEYNINF; }

    // ---- A tile: coalesced load, fused passthrough copy, fp16 + fp32 stage --
    const float4* z4 = (const float4*)(z + (size_t)blockIdx.x * 4096);
    float4* o4 = (float4*)(zq_out + (size_t)blockIdx.x * 4096);
    #pragma unroll
    for (int i = 0; i < 4; i++) {
        int f = tid + i * 256;
        float4 v = z4[f];
        if (do_zq) o4[f] = v;
        int w = f >> 4, c0 = (f & 15) << 2;
        float av[4] = {v.x, v.y, v.z, v.w};
        #pragma unroll
        for (int j = 0; j < 4; j++) {
            int c = c0 + j;
            A16[c * APITCH + w] = __float2half_rn(av[j]);
            A32[c * A32P + w]   = av[j];
        }
    }
    __syncthreads();   // A16/A32 visible

    // rowsum (order-free: affects only the loss, tol 1e-3) + certified T
    if (tid < 64) {
        const float* ap = A32 + tid * A32P;
        float s = 0.f, l1 = 0.f;
        #pragma unroll
        for (int w = 0; w < 64; w++) {
            float a = ap[w];
            s = __fadd_rn(s, __fmul_rn(a, a));
            l1 += fabsf(a);
        }
        rowsum_s[tid] = s;
        rowthr_s[tid] = 2.0e-3f * l1 + 0.08f;   // T >= 2W + 512*esum_max
    }
    __syncthreads();

    // loop-invariant per-slot row ids and thresholds (hoisted out of mainloop)
    int rowv[4];
    float rthr[4];
    #pragma unroll
    for (int mt = 0; mt < 2; mt++)
        #pragma unroll
        for (int h = 0; h < 2; h++) {
            int r = mw * 32 + mt * 16 + h * 8 + (lane >> 2);
            rowv[mt * 2 + h] = r;
            rthr[mt * 2 + h] = rowthr_s[r];
        }

    const uint32_t Abase = smem_u32(A16);
    const uint32_t arow  = (uint32_t)(mw * 32 + (lane & 15));
    const uint32_t acol8 = (uint32_t)((lane >> 4) << 3);

    // ---- 8 chunks x 128 codes (16 KB staged, double-buffered) ---------------
    #pragma unroll 1
    for (int chunk = 0; chunk < 8; chunk++) {
        const int buf = chunk & 1;
        if (chunk + 1 < 8) {
            const char* src = (const char*)g_Bimg + (size_t)(chunk + 1) * 16384;
            const uint32_t dst = sB + (buf ^ 1) * 16384;
            #pragma unroll
            for (int i = 0; i < 4; i++)
                cpasync16(dst + tid * 16 + i * 4096, src + tid * 16 + i * 4096);
            asm volatile("cp.async.commit_group;" ::: "memory");
            asm volatile("cp.async.wait_group 1;" ::: "memory");
        } else {
            asm volatile("cp.async.wait_group 0;" ::: "memory");
        }
        __syncthreads();   // single barrier per chunk: buf staged for all warps
                           // (also orders chunk-2 reads before this overwrite)

        const uint32_t bp = sB + buf * 16384 + (uint32_t)lane * 16;
        float acc[2][4][4];
        #pragma unroll
        for (int mt = 0; mt < 2; mt++)
            #pragma unroll
            for (int nt = 0; nt < 4; nt++)
                #pragma unroll
                for (int r = 0; r < 4; r++) acc[mt][nt][r] = 0.f;

        // batched bb loads (MLP) then MMA block — R8-proven ordering
        #pragma unroll
        for (int k32 = 0; k32 < 2; k32++) {
            uint4 bb[4];
            #pragma unroll
            for (int nt = 0; nt < 4; nt++) {
                uint32_t addr = bp + (uint32_t)((((nw * 4 + nt) << 1) + k32) * 512);
                asm volatile("ld.shared.v4.u32 {%0,%1,%2,%3}, [%4];"
                    : "=r"(bb[nt].x), "=r"(bb[nt].y), "=r"(bb[nt].z), "=r"(bb[nt].w)
                    : "r"(addr));
            }
            #pragma unroll
            for (int mt = 0; mt < 2; mt++) {
                uint32_t a0[4], a1[4];
                uint32_t ad = Abase + ((arow + mt * 16) * APITCH
                                       + (uint32_t)(k32 * 32) + acol8) * 2;
                ldsm4(a0, ad);
                ldsm4(a1, ad + 32);
                #pragma unroll
                for (int nt = 0; nt < 4; nt++) {
                    mma16816(acc[mt][nt], a0, bb[nt].x, bb[nt].y);
                    mma16816(acc[mt][nt], a1, bb[nt].z, bb[nt].w);
                }
            }
        }

        // ---- epilogue: one return-value atomicMax per slot + appends --------
        const int knb = chunk * 128 + nw * 32;
        #pragma unroll
        for (int mt = 0; mt < 2; mt++)
            #pragma unroll
            for (int h = 0; h < 2; h++) {
                const int slot = mt * 2 + h;
                float lanemax = __uint_as_float(FNINF);
                #pragma unroll
                for (int nt = 0; nt < 4; nt++)
                    #pragma unroll
                    for (int j = 0; j < 2; j++)
                        lanemax = fmaxf(lanemax, acc[mt][nt][h * 2 + j]);
                uint32_t old = atomicMax(&s_gkey[rowv[slot]], fkey(lanemax));
                const float cut = fmaxf(funkey(old), lanemax) - rthr[slot];
                if (lanemax >= cut) {          // skip append scan when impossible
                    #pragma unroll
                    for (int nt = 0; nt < 4; nt++)
                        #pragma unroll
                        for (int j = 0; j < 2; j++) {
                            float v = acc[mt][nt][h * 2 + j];
                            if (v >= cut) {
                                int k = knb + nt * 8 + q * 2 + j;
                                int sc = atomicAdd(&cnt_s[rowv[slot]], 1);
                                if (sc < CAP)
                                    cand[rowv[slot] * CAP + sc] =
                                        ((unsigned long long)__float_as_uint(v) << 32)
                                        | (unsigned)k;
                            }
                        }
                }
            }
    }
    __syncthreads();   // s_gkey/cand/cnt final

    // ---- exact rescoring of certified candidates (4 threads per row) --------
    {
        const int row = tid >> 2, sub = tid & 3;
        const float gmax = funkey(s_gkey[row]);   // exact block max
        const float cut = gmax - rowthr_s[row];
        const float rv  = rowsum_s[row];
        const float* arow32 = A32 + row * A32P;
        const int n = cnt_s[row];
        unsigned long long bu = ~0ull;

        if (n <= CAP) {
            for (int i = sub; i < n; i += 4) {
                unsigned long long u = cand[row * CAP + i];
                float v = __uint_as_float((uint32_t)(u >> 32));
                if (v >= cut) {
                    int k = (int)(uint32_t)u;
                    float dot = dot64(arow32, (const float4*)(emb + k * 64));
                    float d2 = __fadd_rn(__fmaf_rn(-2.f, dot, rv), esum_s[k]);
                    unsigned long long uu =
                        ((unsigned long long)__float_as_uint(d2) << 32) | (unsigned)k;
                    if (uu < bu) bu = uu;
                }
            }
        } else {
            // overflow fallback (rare): exact scan of all 1024 codes
            for (int k = sub; k < 1024; k += 4) {
                float dot = dot64(arow32, (const float4*)(emb + k * 64));
                float d2 = __fadd_rn(__fmaf_rn(-2.f, dot, rv), esum_s[k]);
                unsigned long long uu =
                    ((unsigned long long)__float_as_uint(d2) << 32) | (unsigned)k;
                if (uu < bu) bu = uu;
            }
        }
        // merge the 4 sub-threads (consecutive lanes)
        unsigned long long o = __shfl_xor_sync(0xffffffffu, bu, 1);
        if (o < bu) bu = o;
        o = __shfl_xor_sync(0xffffffffu, bu, 2);
        if (o < bu) bu = o;

        if (sub == 0) {
            int bi = (int)(uint32_t)bu;
            if (do_idx) {
                int b = blockIdx.x >> 6, hh = blockIdx.x & 63;
                idx_out[((size_t)((b << 6) + row)) * 64 + hh] = (float)bi;
            }
            s_bv[row] = __uint_as_float((uint32_t)(bu >> 32));
        }
    }
    __syncthreads();
    if (tid == 0) {
        float s = 0.f;
        #pragma unroll
        for (int r = 0; r < 64; r++) s += s_bv[r];   // fixed order
        g_losspart[blockIdx.x] = s;
    }

    // ---- fused loss: deterministic last-block reduction ----------------------
    __threadfence();
    if (tid == 0) s_last = (atomicAdd(&g_ctr, 1) == NCTA - 1);
    __syncthreads();
    if (s_last) {
        __threadfence();
        float a = 0.f;
        #pragma unroll
        for (int i = 0; i < 8; i++) a += g_losspart[tid * 8 + i];
        float* red = (float*)cand;
        red[tid] = a;
        __syncthreads();
        for (int st = 128; st > 0; st >>= 1) {
            if (tid < st) red[tid] += red[tid + st];
            __syncthreads();
        }
        if (tid == 0) {
            if (do_loss) loss_out[0] = 0.25f * (red[0] / 8388608.f);
            atomicExch(&g_ctr, 0);   // reset for next graph replay
        }
    }
}

// ---------------------------------------------------------------------------
extern "C" void kernel_launch(void* const* d_in, const int* in_sizes, int n_in,
                              void* d_out, int out_size) {
    const float* z   = (const float*)d_in[0];
    const float* emb = (const float*)d_in[1];
    if (n_in >= 2 && in_sizes[0] < in_sizes[1]) {
        z   = (const float*)d_in[1];
        emb = (const float*)d_in[0];
    }

    float* out = (float*)d_out;
    const long long ZQ = 8388608LL;
    const long long NI = 131072LL;
    const int do_zq   = (long long)out_size >= ZQ;
    const int do_idx  = (long long)out_size >= ZQ + NI;
    const int do_loss = (long long)out_size >= ZQ + NI + 1;

    cudaFuncSetAttribute(vq_main, cudaFuncAttributeMaxDynamicSharedMemorySize, DSMEM);

    vq_prep<<<129, 256>>>(emb);
    vq_main<<<NCTA, 256, DSMEM>>>(z, emb,
                                  do_zq ? out : nullptr,
                                  do_idx ? out + ZQ : nullptr,
                                  do_loss ? out + ZQ + NI : nullptr,
                                  do_zq, do_idx, do_loss);
}

// round 16
// speedup vs baseline: 1.1709x; 1.1709x over previous
#include <cuda_runtime.h>
#include <cuda_fp16.h>
#include <cstdint>

// ---------------------------------------------------------------------------
// VectorQuantizer on GB300 (sm_103a, compute_103 PTX) — single-pass fp16 MMA.
// 3 CTAs/SM (occ 37.5%): 8 x 128-code chunks, acc=32 regs. Block-shared
// running max via return-value atomicMax. Certified appends ~5/row; exact
// fp32 rescoring + fused loss. R16: merged prep with R14's work distribution
// (blocks 0-3 esum, blocks 4-131 B image) — 2-launch chain, no straggler.
// ---------------------------------------------------------------------------

#define NCTA 2048
#define APITCH 72      // halves per A row (144 B; conflict-free ldmatrix)
#define A32P 65        // floats per A32 row
#define CAP 20         // candidate list capacity per row
#define FNINF 0xFF800000u
#define KEYNINF 0x007FFFFFu   // fkey(-inf)

// dynamic smem layout (bytes)
#define OFF_A16   0            // 64 * 144          =  9216
#define OFF_A32   9216         // 64 * 65 * 4       = 16640
#define OFF_CAND  25856        // 64 * 20 * 8       = 10240
#define OFF_ESUM  36096        // 1024 * 4          =  4096
#define OFF_B     40192        // 2 * 16384         = 32768
#define DSMEM     72960

__device__ __align__(16) __half g_Bimg[65536];   // 256 tiles(n8 x k32) * 512 B
__device__ __align__(16) float  g_esum[1024];
__device__ float g_losspart[NCTA];
__device__ int   g_ctr = 0;

__device__ __forceinline__ uint32_t smem_u32(const void* p) {
    uint32_t a;
    asm("{ .reg .u64 t; cvta.to.shared.u64 t, %1; cvt.u32.u64 %0, t; }" : "=r"(a) : "l"(p));
    return a;
}
__device__ __forceinline__ uint32_t fkey(float f) {          // monotonic float->uint
    uint32_t u = __float_as_uint(f);
    return u ^ ((u >> 31) ? 0xFFFFFFFFu : 0x80000000u);
}
__device__ __forceinline__ float funkey(uint32_t k) {        // inverse
    uint32_t u = (k & 0x80000000u) ? (k ^ 0x80000000u) : ~k;
    return __uint_as_float(u);
}
__device__ __forceinline__ void ldsm4(uint32_t a[4], uint32_t addr) {
    asm volatile("ldmatrix.sync.aligned.m8n8.x4.shared.b16 {%0,%1,%2,%3}, [%4];"
        : "=r"(a[0]), "=r"(a[1]), "=r"(a[2]), "=r"(a[3]) : "r"(addr));
}
__device__ __forceinline__ void mma16816(float c[4], const uint32_t a[4],
                                         uint32_t b0, uint32_t b1) {
    asm volatile("mma.sync.aligned.m16n8k16.row.col.f32.f16.f16.f32 "
        "{%0,%1,%2,%3}, {%4,%5,%6,%7}, {%8,%9}, {%0,%1,%2,%3};"
        : "+f"(c[0]), "+f"(c[1]), "+f"(c[2]), "+f"(c[3])
        : "r"(a[0]), "r"(a[1]), "r"(a[2]), "r"(a[3]), "r"(b0), "r"(b1));
}
__device__ __forceinline__ void cpasync16(uint32_t sdst, const void* gsrc) {
    asm volatile("cp.async.cg.shared.global [%0], [%1], 16;" :: "r"(sdst), "l"(gsrc) : "memory");
}

// exact fp32 dot of a 64-elem row pair using float4 loads (L1-friendly)
__device__ __forceinline__ float dot64(const float* __restrict__ a,
                                       const float4* __restrict__ e4) {
    float dot = 0.f;
    #pragma unroll
    for (int i = 0; i < 16; i++) {
        float4 e = __ldg(e4 + i);
        dot = __fmaf_rn(a[i * 4 + 0], e.x, dot);
        dot = __fmaf_rn(a[i * 4 + 1], e.y, dot);
        dot = __fmaf_rn(a[i * 4 + 2], e.z, dot);
        dot = __fmaf_rn(a[i * 4 + 3], e.w, dot);
    }
    return dot;
}

// ---- merged prep, R14 work distribution:
//   blocks 0-3   : esum, one code per thread (exact R1 formula)
//   blocks 4-131 : B image (bhi only) in exact mma-fragment order
__global__ void vq_prep(const float* __restrict__ emb) {
    if (blockIdx.x < 4) {
        int k = blockIdx.x * 256 + threadIdx.x;
        float s = 0.f;
        #pragma unroll
        for (int d = 0; d < 64; d++) {
            float e = emb[k * 64 + d];
            s = __fadd_rn(s, __fmul_rn(e, e));
        }
        g_esum[k] = s;
        return;
    }
    int p = (blockIdx.x - 4) * 256 + threadIdx.x;   // 32768 u32 slots
    int tile = p >> 7, u = p & 127;
    int l = u >> 2, r = u & 3;
    int nt = tile >> 1, ks32 = tile & 1;
    int n = nt * 8 + (l >> 2);
    int q = l & 3;
    int kk = ks32 * 32 + ((r >> 1) << 4) + ((r & 1) << 3) + q * 2;
    __half2 out;
    #pragma unroll
    for (int j = 0; j < 2; j++) {
        int w = kk + j;
        float b = __fmul_rn(emb[n * 64 + w], 1024.0f);   // exact (2^10)
        if (j == 0) out.x = __float2half_rn(b); else out.y = __float2half_rn(b);
    }
    ((__half2*)g_Bimg)[p] = out;
}

// ---- main --------------------------------------------------------------------
__global__ void __launch_bounds__(256, 3)
vq_main(const float* __restrict__ z, const float* __restrict__ emb,
        float* __restrict__ zq_out, float* __restrict__ idx_out,
        float* __restrict__ loss_out, int do_zq, int do_idx, int do_loss) {
    extern __shared__ __align__(16) char dsm[];
    __half* A16 = (__half*)(dsm + OFF_A16);
    float*  A32 = (float*)(dsm + OFF_A32);
    unsigned long long* cand = (unsigned long long*)(dsm + OFF_CAND);
    float* esum_s = (float*)(dsm + OFF_ESUM);
    const uint32_t sB = smem_u32(dsm) + OFF_B;

    __shared__ float rowsum_s[64], rowthr_s[64];
    __shared__ uint32_t s_gkey[64];
    __shared__ int   cnt_s[64];
    __shared__ float s_bv[64];
    __shared__ int   s_last;

    const int tid = threadIdx.x, wid = tid >> 5, lane = tid & 31;
    const int mw = wid >> 2, nw = wid & 3;
    const int q = lane & 3;

    // ---- prefetch B chunk 0 FIRST so it overlaps the z prologue -------------
    {
        const char* src = (const char*)g_Bimg;
        #pragma unroll
        for (int i = 0; i < 4; i++)
            cpasync16(sB + tid * 16 + i * 4096, src + tid * 16 + i * 4096);
        asm volatile("cp.async.commit_group;" ::: "memory");
    }

    for (int i = tid; i < 1024; i += 256) esum_s[i] = g_esum[i];
    if (tid < 64) { cnt_s[tid] = 0; s_gkey[tid] = KEYNINF; }

    // ---- A tile: coalesced load, fused passthrough copy, fp16 + fp32 stage --
    const float4* z4 = (const float4*)(z + (size_t)blockIdx.x * 4096);
    float4* o4 = (float4*)(zq_out + (size_t)blockIdx.x * 4096);
    #pragma unroll
    for (int i = 0; i < 4; i++) {
        int f = tid + i * 256;
        float4 v = z4[f];
        if (do_zq) o4[f] = v;
        int w = f >> 4, c0 = (f & 15) << 2;
        float av[4] = {v.x, v.y, v.z, v.w};
        #pragma unroll
        for (int j = 0; j < 4; j++) {
            int c = c0 + j;
            A16[c * APITCH + w] = __float2half_rn(av[j]);
            A32[c * A32P + w]   = av[j];
        }
    }
    __syncthreads();   // A16/A32 visible

    // rowsum (order-free: affects only the loss, tol 1e-3) + certified T
    if (tid < 64) {
        const float* ap = A32 + tid * A32P;
        float s = 0.f, l1 = 0.f;
        #pragma unroll
        for (int w = 0; w < 64; w++) {
            float a = ap[w];
            s = __fadd_rn(s, __fmul_rn(a, a));
            l1 += fabsf(a);
        }
        rowsum_s[tid] = s;
        rowthr_s[tid] = 2.0e-3f * l1 + 0.08f;   // T >= 2W + 512*esum_max
    }
    __syncthreads();

    // loop-invariant per-slot row ids and thresholds (hoisted out of mainloop)
    int rowv[4];
    float rthr[4];
    #pragma unroll
    for (int mt = 0; mt < 2; mt++)
        #pragma unroll
        for (int h = 0; h < 2; h++) {
            int r = mw * 32 + mt * 16 + h * 8 + (lane >> 2);
            rowv[mt * 2 + h] = r;
            rthr[mt * 2 + h] = rowthr_s[r];
        }

    const uint32_t Abase = smem_u32(A16);
    const uint32_t arow  = (uint32_t)(mw * 32 + (lane & 15));
    const uint32_t acol8 = (uint32_t)((lane >> 4) << 3);

    // ---- 8 chunks x 128 codes (16 KB staged, double-buffered) ---------------
    #pragma unroll 1
    for (int chunk = 0; chunk < 8; chunk++) {
        const int buf = chunk & 1;
        if (chunk + 1 < 8) {
            const char* src = (const char*)g_Bimg + (size_t)(chunk + 1) * 16384;
            const uint32_t dst = sB + (buf ^ 1) * 16384;
            #pragma unroll
            for (int i = 0; i < 4; i++)
                cpasync16(dst + tid * 16 + i * 4096, src + tid * 16 + i * 4096);
            asm volatile("cp.async.commit_group;" ::: "memory");
            asm volatile("cp.async.wait_group 1;" ::: "memory");
        } else {
            asm volatile("cp.async.wait_group 0;" ::: "memory");
        }
        __syncthreads();   // single barrier per chunk: buf staged for all warps
                           // (also orders chunk-2 reads before this overwrite)

        const uint32_t bp = sB + buf * 16384 + (uint32_t)lane * 16;
        float acc[2][4][4];
        #pragma unroll
        for (int mt = 0; mt < 2; mt++)
            #pragma unroll
            for (int nt = 0; nt < 4; nt++)
                #pragma unroll
                for (int r = 0; r < 4; r++) acc[mt][nt][r] = 0.f;

        // batched bb loads (MLP) then MMA block — R8-proven ordering
        #pragma unroll
        for (int k32 = 0; k32 < 2; k32++) {
            uint4 bb[4];
            #pragma unroll
            for (int nt = 0; nt < 4; nt++) {
                uint32_t addr = bp + (uint32_t)((((nw * 4 + nt) << 1) + k32) * 512);
                asm volatile("ld.shared.v4.u32 {%0,%1,%2,%3}, [%4];"
                    : "=r"(bb[nt].x), "=r"(bb[nt].y), "=r"(bb[nt].z), "=r"(bb[nt].w)
                    : "r"(addr));
            }
            #pragma unroll
            for (int mt = 0; mt < 2; mt++) {
                uint32_t a0[4], a1[4];
                uint32_t ad = Abase + ((arow + mt * 16) * APITCH
                                       + (uint32_t)(k32 * 32) + acol8) * 2;
                ldsm4(a0, ad);
                ldsm4(a1, ad + 32);
                #pragma unroll
                for (int nt = 0; nt < 4; nt++) {
                    mma16816(acc[mt][nt], a0, bb[nt].x, bb[nt].y);
                    mma16816(acc[mt][nt], a1, bb[nt].z, bb[nt].w);
                }
            }
        }

        // ---- epilogue: one return-value atomicMax per slot + appends --------
        const int knb = chunk * 128 + nw * 32;
        #pragma unroll
        for (int mt = 0; mt < 2; mt++)
            #pragma unroll
            for (int h = 0; h < 2; h++) {
                const int slot = mt * 2 + h;
                float lanemax = __uint_as_float(FNINF);
                #pragma unroll
                for (int nt = 0; nt < 4; nt++)
                    #pragma unroll
                    for (int j = 0; j < 2; j++)
                        lanemax = fmaxf(lanemax, acc[mt][nt][h * 2 + j]);
                uint32_t old = atomicMax(&s_gkey[rowv[slot]], fkey(lanemax));
                const float cut = fmaxf(funkey(old), lanemax) - rthr[slot];
                if (lanemax >= cut) {          // skip append scan when impossible
                    #pragma unroll
                    for (int nt = 0; nt < 4; nt++)
                        #pragma unroll
                        for (int j = 0; j < 2; j++) {
                            float v = acc[mt][nt][h * 2 + j];
                            if (v >= cut) {
                                int k = knb + nt * 8 + q * 2 + j;
                                int sc = atomicAdd(&cnt_s[rowv[slot]], 1);
                                if (sc < CAP)
                                    cand[rowv[slot] * CAP + sc] =
                                        ((unsigned long long)__float_as_uint(v) << 32)
                                        | (unsigned)k;
                            }
                        }
                }
            }
    }
    __syncthreads();   // s_gkey/cand/cnt final

    // ---- exact rescoring of certified candidates (4 threads per row) --------
    {
        const int row = tid >> 2, sub = tid & 3;
        const float gmax = funkey(s_gkey[row]);   // exact block max
        const float cut = gmax - rowthr_s[row];
        const float rv  = rowsum_s[row];
        const float* arow32 = A32 + row * A32P;
        const int n = cnt_s[row];
        unsigned long long bu = ~0ull;

        if (n <= CAP) {
            for (int i = sub; i < n; i += 4) {
                unsigned long long u = cand[row * CAP + i];
                float v = __uint_as_float((uint32_t)(u >> 32));
                if (v >= cut) {
                    int k = (int)(uint32_t)u;
                    float dot = dot64(arow32, (const float4*)(emb + k * 64));
                    float d2 = __fadd_rn(__fmaf_rn(-2.f, dot, rv), esum_s[k]);
                    unsigned long long uu =
                        ((unsigned long long)__float_as_uint(d2) << 32) | (unsigned)k;
                    if (uu < bu) bu = uu;
                }
            }
        } else {
            // overflow fallback (rare): exact scan of all 1024 codes
            for (int k = sub; k < 1024; k += 4) {
                float dot = dot64(arow32, (const float4*)(emb + k * 64));
                float d2 = __fadd_rn(__fmaf_rn(-2.f, dot, rv), esum_s[k]);
                unsigned long long uu =
                    ((unsigned long long)__float_as_uint(d2) << 32) | (unsigned)k;
                if (uu < bu) bu = uu;
            }
        }
        // merge the 4 sub-threads (consecutive lanes)
        unsigned long long o = __shfl_xor_sync(0xffffffffu, bu, 1);
        if (o < bu) bu = o;
        o = __shfl_xor_sync(0xffffffffu, bu, 2);
        if (o < bu) bu = o;

        if (sub == 0) {
            int bi = (int)(uint32_t)bu;
            if (do_idx) {
                int b = blockIdx.x >> 6, hh = blockIdx.x & 63;
                idx_out[((size_t)((b << 6) + row)) * 64 + hh] = (float)bi;
            }
            s_bv[row] = __uint_as_float((uint32_t)(bu >> 32));
        }
    }
    __syncthreads();
    if (tid == 0) {
        float s = 0.f;
        #pragma unroll
        for (int r = 0; r < 64; r++) s += s_bv[r];   // fixed order
        g_losspart[blockIdx.x] = s;
    }

    // ---- fused loss: deterministic last-block reduction ----------------------
    __threadfence();
    if (tid == 0) s_last = (atomicAdd(&g_ctr, 1) == NCTA - 1);
    __syncthreads();
    if (s_last) {
        __threadfence();
        float a = 0.f;
        #pragma unroll
        for (int i = 0; i < 8; i++) a += g_losspart[tid * 8 + i];
        float* red = (float*)cand;
        red[tid] = a;
        __syncthreads();
        for (int st = 128; st > 0; st >>= 1) {
            if (tid < st) red[tid] += red[tid + st];
            __syncthreads();
        }
        if (tid == 0) {
            if (do_loss) loss_out[0] = 0.25f * (red[0] / 8388608.f);
            atomicExch(&g_ctr, 0);   // reset for next graph replay
        }
    }
}

// ---------------------------------------------------------------------------
extern "C" void kernel_launch(void* const* d_in, const int* in_sizes, int n_in,
                              void* d_out, int out_size) {
    const float* z   = (const float*)d_in[0];
    const float* emb = (const float*)d_in[1];
    if (n_in >= 2 && in_sizes[0] < in_sizes[1]) {
        z   = (const float*)d_in[1];
        emb = (const float*)d_in[0];
    }

    float* out = (float*)d_out;
    const long long ZQ = 8388608LL;
    const long long NI = 131072LL;
    const int do_zq   = (long long)out_size >= ZQ;
    const int do_idx  = (long long)out_size >= ZQ + NI;
    const int do_loss = (long long)out_size >= ZQ + NI + 1;

    cudaFuncSetAttribute(vq_main, cudaFuncAttributeMaxDynamicSharedMemorySize, DSMEM);

    vq_prep<<<132, 256>>>(emb);
    vq_main<<<NCTA, 256, DSMEM>>>(z, emb,
                                  do_zq ? out : nullptr,
                                  do_idx ? out + ZQ : nullptr,
                                  do_loss ? out + ZQ + NI : nullptr,
                                  do_zq, do_idx, do_loss);
}